// round 7
// baseline (speedup 1.0000x reference)
#include <cuda_runtime.h>

#define NQ 12
#define DIM 4096
#define NLAYERS 3
#define NGATES (NLAYERS * NQ)   // 36
#define TPB 256
#define RPT 16                  // register amplitudes per thread (per packed pair)
#define BUF (DIM + DIM / 16)    // 4352 u64 per component, addr(j)=j+(j>>4)

typedef unsigned long long u64;

// Pre-packed gate coefficients: 36 gates x 12 float2 (duplicated / negated-duplicated)
__device__ float2 g_gates2[NGATES * 12];

// ---------------- f32x2 helpers (sm_103a packed fp32) ----------------
__device__ __forceinline__ u64 pk2(float x, float y) {
    u64 r; asm("mov.b64 %0, {%1, %2};" : "=l"(r) : "f"(x), "f"(y)); return r;
}
__device__ __forceinline__ void unpk2(u64 a, float& x, float& y) {
    asm("mov.b64 {%0, %1}, %2;" : "=f"(x), "=f"(y) : "l"(a));
}
__device__ __forceinline__ u64 f2fma(u64 a, u64 b, u64 c) {
    u64 d; asm("fma.rn.f32x2 %0, %1, %2, %3;" : "=l"(d) : "l"(a), "l"(b), "l"(c)); return d;
}
__device__ __forceinline__ u64 f2mul(u64 a, u64 b) {
    u64 d; asm("mul.rn.f32x2 %0, %1, %2;" : "=l"(d) : "l"(a), "l"(b)); return d;
}
__device__ __forceinline__ u64 f2add(u64 a, u64 b) {
    u64 d; asm("add.rn.f32x2 %0, %1, %2;" : "=l"(d) : "l"(a), "l"(b)); return d;
}

// ---------------------------------------------------------------------------
// Prep: fuse RZ*RY*RX per gate; emit 12 duplicated-packed coefficient pairs.
// ---------------------------------------------------------------------------
__global__ void prep_gates(const float* __restrict__ params) {
    int g = blockIdx.x * blockDim.x + threadIdx.x;
    if (g >= NGATES) return;
    float a = params[3 * g + 0] * 0.5f;
    float b = params[3 * g + 1] * 0.5f;
    float c = params[3 * g + 2] * 0.5f;
    float ca = cosf(a), sa = sinf(a);
    float cb = cosf(b), sb = sinf(b);
    float cc = cosf(c), sc = sinf(c);
    float m00r = cb * ca, m00i = sb * sa;
    float m01r = -sb * ca, m01i = -cb * sa;
    float m10r = sb * ca, m10i = -cb * sa;
    float m11r = cb * ca, m11i = -sb * sa;
    float u00r = cc * m00r + sc * m00i, u00i = cc * m00i - sc * m00r;
    float u01r = cc * m01r + sc * m01i, u01i = cc * m01i - sc * m01r;
    float u10r = cc * m10r - sc * m10i, u10i = cc * m10i + sc * m10r;
    float u11r = cc * m11r - sc * m11i, u11i = cc * m11i + sc * m11r;
    float2* o = &g_gates2[g * 12];
    o[0]  = make_float2(u00r, u00r);
    o[1]  = make_float2(-u00i, -u00i);
    o[2]  = make_float2(u01r, u01r);
    o[3]  = make_float2(-u01i, -u01i);
    o[4]  = make_float2(u00i, u00i);
    o[5]  = make_float2(u01i, u01i);
    o[6]  = make_float2(u10r, u10r);
    o[7]  = make_float2(-u10i, -u10i);
    o[8]  = make_float2(u11r, u11r);
    o[9]  = make_float2(-u11i, -u11i);
    o[10] = make_float2(u10i, u10i);
    o[11] = make_float2(u11i, u11i);
}

// Apply 4 gates on the register-index bits (bits 3..0 of r), gate qq on bit (3-qq).
__device__ __forceinline__ void apply4(u64 vre[RPT], u64 vim[RPT],
                                       const u64* __restrict__ sG2, int gbase) {
#pragma unroll
    for (int qq = 0; qq < 4; qq++) {
        const u64* C = &sG2[(gbase + qq) * 12];
        const u64 c0 = C[0], c1 = C[1], c2 = C[2], c3 = C[3], c4 = C[4], c5 = C[5];
        const u64 c6 = C[6], c7 = C[7], c8 = C[8], c9 = C[9], c10 = C[10], c11 = C[11];
        const int mb = 8 >> qq;
#pragma unroll
        for (int r = 0; r < RPT; r++) {
            if (!(r & mb)) {
                const int r1 = r | mb;
                u64 a0re = vre[r],  a0im = vim[r];
                u64 a1re = vre[r1], a1im = vim[r1];
                u64 n0re = f2fma(c0, a0re, f2fma(c1, a0im, f2fma(c2, a1re, f2mul(c3, a1im))));
                u64 n0im = f2fma(c4, a0re, f2fma(c0, a0im, f2fma(c5, a1re, f2mul(c2, a1im))));
                u64 n1re = f2fma(c6, a0re, f2fma(c7, a0im, f2fma(c8, a1re, f2mul(c9, a1im))));
                u64 n1im = f2fma(c10, a0re, f2fma(c6, a0im, f2fma(c11, a1re, f2mul(c8, a1im))));
                vre[r] = n0re; vim[r] = n0im;
                vre[r1] = n1re; vim[r1] = n1im;
            }
        }
    }
}

// ---------------------------------------------------------------------------
// One CTA per BATCH PAIR (u64 packs elt0,elt1). 256 threads x 16 amps.
// Layouts: L0 r={b11..b8} t={b7..b0} | L1 r={b7..b4} t={b11..b8,b3..b0}
//          L2 r={b3..b0}  t={b11..b4}
// Exchange buffer addressing: addr(j) = j + (j>>4)  (conflict-free, verified).
// smem 69.6KB dynamic -> 2 CTAs/SM; reg cap 128 -> no spills.
// ---------------------------------------------------------------------------
extern __shared__ __align__(16) u64 dynsm[];

__global__ __launch_bounds__(TPB, 2) void qsim_kernel(
    const float* __restrict__ x, float* __restrict__ out) {
    __shared__ u64 sG2[NGATES * 12];
    __shared__ u64 sRed[TPB / 32];
    __shared__ float sAcc[2 * NQ];

    u64* bRe = dynsm;
    u64* bIm = dynsm + BUF;

    const int tid = threadIdx.x;
    const int bid = blockIdx.x;
    const float* xb0 = x + (size_t)(2 * bid) * DIM;
    const float* xb1 = xb0 + DIM;

    for (int i = tid; i < NGATES * 12; i += TPB) sG2[i] = ((const u64*)g_gates2)[i];
    if (tid < 2 * NQ) sAcc[tid] = 0.0f;

    // ---- load both elements packed (L0 layout) + per-element sum of squares ----
    u64 vre[RPT], vim[RPT];
    u64 ss = 0;
#pragma unroll
    for (int r = 0; r < RPT; r++) {
        int i = (r << 8) | tid;
        u64 v = pk2(xb0[i], xb1[i]);
        vre[r] = v;
        vim[r] = 0;
        ss = f2fma(v, v, ss);
    }
#pragma unroll
    for (int o = 16; o; o >>= 1) ss = f2add(ss, __shfl_xor_sync(0xffffffffu, ss, o));
    if ((tid & 31) == 0) sRed[tid >> 5] = ss;
    __syncthreads();
    ss = 0;
#pragma unroll
    for (int w = 0; w < TPB / 32; w++) ss = f2add(ss, sRed[w]);
    float s0, s1; unpk2(ss, s0, s1);
    const u64 inv = pk2(rsqrtf(s0), rsqrtf(s1));
#pragma unroll
    for (int r = 0; r < RPT; r++) vre[r] = f2mul(vre[r], inv);

    // ---- exchange address bases (u64 units), addr(j) = j + (j>>4) ----
    const int baseA = tid + (tid >> 4);                                 // X1 write: +r*272 ; also L0-style
    const int baseB = (tid >> 4) * 272 + (tid & 15);                    // L1 read / X2 write: +r*17
    const int baseC = tid * 17;                                         // L2 read / X3 write: +r
    // sigma(t) for low 8 bits (XOR-linear CNOT-ring permutation)
    const int sigt = (tid ^ (tid >> 1)) ^ ((tid & 1) ? 0xC00 : 0);

    // ---- circuit ----
#pragma unroll 1
    for (int layer = 0; layer < NLAYERS; layer++) {
        const int gbase = layer * NQ;

        apply4(vre, vim, sG2, gbase + 0);          // q0..q3 (bits 11..8)
        __syncthreads();                           // prior buffer readers done
#pragma unroll
        for (int r = 0; r < RPT; r++) {            // X1 write: i=(r<<8)|t
            int a = baseA + r * 272;
            bRe[a] = vre[r]; bIm[a] = vim[r];
        }
        __syncthreads();
#pragma unroll
        for (int r = 0; r < RPT; r++) {            // L1 read
            int a = baseB + r * 17;
            vre[r] = bRe[a]; vim[r] = bIm[a];
        }

        apply4(vre, vim, sG2, gbase + 4);          // q4..q7 (bits 7..4)
        __syncthreads();
#pragma unroll
        for (int r = 0; r < RPT; r++) {            // X2 write (canonical, L1 ownership)
            int a = baseB + r * 17;
            bRe[a] = vre[r]; bIm[a] = vim[r];
        }
        __syncthreads();
#pragma unroll
        for (int r = 0; r < RPT; r++) {            // L2 read: j=(t<<4)|r
            int a = baseC + r;
            vre[r] = bRe[a]; vim[r] = bIm[a];
        }

        apply4(vre, vim, sG2, gbase + 8);          // q8..q11 (bits 3..0)
        __syncthreads();
#pragma unroll
        for (int r = 0; r < RPT; r++) {            // X3 write (canonical, L2 ownership)
            int a = baseC + r;
            bRe[a] = vre[r]; bIm[a] = vim[r];
        }
        __syncthreads();
        {
            // gather back to L0 with CNOT-ring sigma folded in
            const int SIGC4[RPT] = {0x000, 0x180, 0x300, 0x280,
                                    0x600, 0x780, 0x500, 0x480,
                                    0xC00, 0xD80, 0xF00, 0xE80,
                                    0xA00, 0xB80, 0x900, 0x880};
#pragma unroll
            for (int r = 0; r < RPT; r++) {
                int j = SIGC4[r] ^ sigt;
                int a = j + (j >> 4);
                vre[r] = bRe[a]; vim[r] = bIm[a];
            }
        }
    }

    // ---- expectations <Z_q>, both elements at once (registers only) ----
    u64 acc[NQ];
#pragma unroll
    for (int q = 0; q < NQ; q++) acc[q] = 0;
#pragma unroll
    for (int r = 0; r < RPT; r++) {
        u64 p2 = f2fma(vre[r], vre[r], f2mul(vim[r], vim[r]));
        u64 pn = p2 ^ 0x8000000080000000ULL;       // exact negation of both halves
        const int i = (r << 8) | tid;
#pragma unroll
        for (int q = 0; q < NQ; q++) {
            acc[q] = f2add(acc[q], ((i >> (11 - q)) & 1) ? pn : p2);
        }
    }
#pragma unroll
    for (int q = 0; q < NQ; q++) {
#pragma unroll
        for (int o = 16; o; o >>= 1)
            acc[q] = f2add(acc[q], __shfl_xor_sync(0xffffffffu, acc[q], o));
    }
    if ((tid & 31) == 0) {
#pragma unroll
        for (int q = 0; q < NQ; q++) {
            float p0, p1; unpk2(acc[q], p0, p1);
            atomicAdd(&sAcc[q], p0);
            atomicAdd(&sAcc[NQ + q], p1);
        }
    }
    __syncthreads();
    if (tid < NQ) {
        out[(size_t)(2 * bid) * NQ + tid] = sAcc[tid];
        out[(size_t)(2 * bid + 1) * NQ + tid] = sAcc[NQ + tid];
    }
}

extern "C" void kernel_launch(void* const* d_in, const int* in_sizes, int n_in,
                              void* d_out, int out_size) {
    const float* x = (const float*)d_in[0];       // (8192, 4096) float32
    const float* params = (const float*)d_in[1];  // (108,) float32
    float* out = (float*)d_out;                   // (8192, 12) float32
    const int batch = in_sizes[0] / DIM;
    const int smem_bytes = 2 * BUF * (int)sizeof(u64); // 69632 -> 2 CTAs/SM

    cudaFuncSetAttribute(qsim_kernel, cudaFuncAttributeMaxDynamicSharedMemorySize,
                         smem_bytes);
    prep_gates<<<1, 64>>>(params);
    qsim_kernel<<<batch / 2, TPB, smem_bytes>>>(x, out);
}

// round 9
// speedup vs baseline: 1.3441x; 1.3441x over previous
#include <cuda_runtime.h>

#define NQ 12
#define DIM 4096
#define NLAYERS 3
#define NGATES (NLAYERS * NQ)   // 36
#define TPB 512
#define RPT 8                   // register amplitudes per thread (per packed pair)
#define STRIDE 9                // padded smem row stride (in 8-byte units)
#define BUF (TPB * STRIDE)      // 4608 u64 per component per buffer

typedef unsigned long long u64;

// Pre-packed gate coefficients: 36 gates x 12 float2 (duplicated / negated-duplicated)
__device__ float2 g_gates2[NGATES * 12];

// ---------------- f32x2 helpers (sm_103a packed fp32) ----------------
__device__ __forceinline__ u64 pk2(float x, float y) {
    u64 r; asm("mov.b64 %0, {%1, %2};" : "=l"(r) : "f"(x), "f"(y)); return r;
}
__device__ __forceinline__ void unpk2(u64 a, float& x, float& y) {
    asm("mov.b64 {%0, %1}, %2;" : "=f"(x), "=f"(y) : "l"(a));
}
__device__ __forceinline__ u64 f2fma(u64 a, u64 b, u64 c) {
    u64 d; asm("fma.rn.f32x2 %0, %1, %2, %3;" : "=l"(d) : "l"(a), "l"(b), "l"(c)); return d;
}
__device__ __forceinline__ u64 f2mul(u64 a, u64 b) {
    u64 d; asm("mul.rn.f32x2 %0, %1, %2;" : "=l"(d) : "l"(a), "l"(b)); return d;
}
__device__ __forceinline__ u64 f2add(u64 a, u64 b) {
    u64 d; asm("add.rn.f32x2 %0, %1, %2;" : "=l"(d) : "l"(a), "l"(b)); return d;
}
__device__ __forceinline__ void bar64(int id) {
    asm volatile("bar.sync %0, 64;" :: "r"(id) : "memory");
}

// ---------------------------------------------------------------------------
// Prep: fuse RZ*RY*RX per gate; emit 12 duplicated-packed coefficient pairs.
// ---------------------------------------------------------------------------
__global__ void prep_gates(const float* __restrict__ params) {
    int g = blockIdx.x * blockDim.x + threadIdx.x;
    if (g >= NGATES) return;
    float a = params[3 * g + 0] * 0.5f;
    float b = params[3 * g + 1] * 0.5f;
    float c = params[3 * g + 2] * 0.5f;
    float ca = cosf(a), sa = sinf(a);
    float cb = cosf(b), sb = sinf(b);
    float cc = cosf(c), sc = sinf(c);
    float m00r = cb * ca, m00i = sb * sa;
    float m01r = -sb * ca, m01i = -cb * sa;
    float m10r = sb * ca, m10i = -cb * sa;
    float m11r = cb * ca, m11i = -sb * sa;
    float u00r = cc * m00r + sc * m00i, u00i = cc * m00i - sc * m00r;
    float u01r = cc * m01r + sc * m01i, u01i = cc * m01i - sc * m01r;
    float u10r = cc * m10r - sc * m10i, u10i = cc * m10i + sc * m10r;
    float u11r = cc * m11r - sc * m11i, u11i = cc * m11i + sc * m11r;
    float2* o = &g_gates2[g * 12];
    o[0]  = make_float2(u00r, u00r);
    o[1]  = make_float2(-u00i, -u00i);
    o[2]  = make_float2(u01r, u01r);
    o[3]  = make_float2(-u01i, -u01i);
    o[4]  = make_float2(u00i, u00i);
    o[5]  = make_float2(u01i, u01i);
    o[6]  = make_float2(u10r, u10r);
    o[7]  = make_float2(-u10i, -u10i);
    o[8]  = make_float2(u11r, u11r);
    o[9]  = make_float2(-u11i, -u11i);
    o[10] = make_float2(u10i, u10i);
    o[11] = make_float2(u11i, u11i);
}

// Apply 3 gates on the register-index bits (bit2,1,0 of r) for a packed batch-pair.
__device__ __forceinline__ void apply3(u64 vre[RPT], u64 vim[RPT],
                                       const u64* __restrict__ sG2, int gbase) {
#pragma unroll
    for (int qq = 0; qq < 3; qq++) {
        const u64* C = &sG2[(gbase + qq) * 12];
        const u64 c0 = C[0], c1 = C[1], c2 = C[2], c3 = C[3], c4 = C[4], c5 = C[5];
        const u64 c6 = C[6], c7 = C[7], c8 = C[8], c9 = C[9], c10 = C[10], c11 = C[11];
        const int mb = 4 >> qq;
#pragma unroll
        for (int r = 0; r < RPT; r++) {
            if (!(r & mb)) {
                const int r1 = r | mb;
                u64 a0re = vre[r],  a0im = vim[r];
                u64 a1re = vre[r1], a1im = vim[r1];
                u64 n0re = f2fma(c0, a0re, f2fma(c1, a0im, f2fma(c2, a1re, f2mul(c3, a1im))));
                u64 n0im = f2fma(c4, a0re, f2fma(c0, a0im, f2fma(c5, a1re, f2mul(c2, a1im))));
                u64 n1re = f2fma(c6, a0re, f2fma(c7, a0im, f2fma(c8, a1re, f2mul(c9, a1im))));
                u64 n1im = f2fma(c10, a0re, f2fma(c6, a0im, f2fma(c11, a1re, f2mul(c8, a1im))));
                vre[r] = n0re; vim[r] = n0im;
                vre[r1] = n1re; vim[r1] = n1im;
            }
        }
    }
}

// ---------------------------------------------------------------------------
// One CTA per BATCH PAIR (u64 packs elt0,elt1). 512 thr x 8 packed amps.
// Layouts: L0 r={b11,b10,b9} | L1 r={b8,b7,b6} | L2 r={b5,b4,b3} | L3 r={b2,b1,b0}
// Exchange scopes (communication footprint):
//   X1 (L0->L1): cross tid bits 8..6  -> __syncthreads      (buffer A)
//   X2 (L1->L2): cross tid bits 5..3  -> bar.sync 64-group  (buffer B)
//   X3 (L2->L3): cross tid bits 2..0  -> __syncwarp         (buffer A)
//   X4 (L3->L0 + sigma): global        -> __syncthreads      (buffer B)
// A,B,A,B alternation makes all pre-write barriers redundant.
// ---------------------------------------------------------------------------
extern __shared__ __align__(16) u64 dynsm[];

__global__ __launch_bounds__(TPB, 1) void qsim_kernel(
    const float* __restrict__ x, float* __restrict__ out) {
    __shared__ u64 sG2[NGATES * 12];
    __shared__ u64 sRed[TPB / 32];
    __shared__ float sAcc[2 * NQ];

    u64* bReA = dynsm;
    u64* bImA = dynsm + BUF;
    u64* bReB = dynsm + 2 * BUF;
    u64* bImB = dynsm + 3 * BUF;

    const int tid = threadIdx.x;
    const int bid = blockIdx.x;
    const float* xb0 = x + (size_t)(2 * bid) * DIM;
    const float* xb1 = xb0 + DIM;

    if (tid < NGATES * 12) sG2[tid] = ((const u64*)g_gates2)[tid];
    if (tid < 2 * NQ) sAcc[tid] = 0.0f;

    // ---- load both elements packed (L0) + per-element sum of squares ----
    u64 vre[RPT], vim[RPT];
    u64 ss = 0;
#pragma unroll
    for (int r = 0; r < RPT; r++) {
        int i = (r << 9) | tid;
        u64 v = pk2(xb0[i], xb1[i]);
        vre[r] = v;
        vim[r] = 0;
        ss = f2fma(v, v, ss);
    }
#pragma unroll
    for (int o = 16; o; o >>= 1) ss = f2add(ss, __shfl_xor_sync(0xffffffffu, ss, o));
    if ((tid & 31) == 0) sRed[tid >> 5] = ss;
    __syncthreads();
    ss = 0;
#pragma unroll
    for (int w = 0; w < TPB / 32; w++) ss = f2add(ss, sRed[w]);
    float s0, s1; unpk2(ss, s0, s1);
    const u64 inv = pk2(rsqrtf(s0), rsqrtf(s1));
#pragma unroll
    for (int r = 0; r < RPT; r++) vre[r] = f2mul(vre[r], inv);

    // exchange write bases (u64 units)
    const int base1 = (tid & 63) * STRIDE + ((tid >> 6) & 7);                      // +r*576
    const int base2 = (((tid >> 6) << 6) | (tid & 7)) * STRIDE + ((tid >> 3) & 7); // +r*72
    const int base3 = (tid >> 3) * (8 * STRIDE) + (tid & 7);                       // +r*9
    const int baseR = tid * STRIDE;                                                // canonical rows
    const int mybar = 1 + (tid >> 6);                                              // named barrier id 1..8
    // sigma(t): XOR-linear CNOT-ring permutation (verified R5)
    const int sig_t = ((tid ^ (tid >> 1)) & 0x0FF) | (tid & 0x100)
                    | ((tid & 1) ? 0xC00 : 0);

    // ---- circuit ----
#pragma unroll 1
    for (int layer = 0; layer < NLAYERS; layer++) {
        const int gbase = layer * NQ;

        apply3(vre, vim, sG2, gbase + 0);          // bits 11,10,9
#pragma unroll
        for (int r = 0; r < RPT; r++) {            // X1 write -> A (global shuffle)
            int a = base1 + r * (64 * STRIDE);
            bReA[a] = vre[r]; bImA[a] = vim[r];
        }
        __syncthreads();
#pragma unroll
        for (int r = 0; r < RPT; r++) {
            int a = baseR + r;
            vre[r] = bReA[a]; vim[r] = bImA[a];
        }

        apply3(vre, vim, sG2, gbase + 3);          // bits 8,7,6
#pragma unroll
        for (int r = 0; r < RPT; r++) {            // X2 write -> B (64-thread groups)
            int a = base2 + r * (8 * STRIDE);
            bReB[a] = vre[r]; bImB[a] = vim[r];
        }
        bar64(mybar);
#pragma unroll
        for (int r = 0; r < RPT; r++) {
            int a = baseR + r;
            vre[r] = bReB[a]; vim[r] = bImB[a];
        }

        apply3(vre, vim, sG2, gbase + 6);          // bits 5,4,3
#pragma unroll
        for (int r = 0; r < RPT; r++) {            // X3 write -> A (8-thread groups, in-warp)
            int a = base3 + r * STRIDE;
            bReA[a] = vre[r]; bImA[a] = vim[r];
        }
        __syncwarp();
#pragma unroll
        for (int r = 0; r < RPT; r++) {
            int a = baseR + r;
            vre[r] = bReA[a]; vim[r] = bImA[a];
        }

        apply3(vre, vim, sG2, gbase + 9);          // bits 2,1,0
#pragma unroll
        for (int r = 0; r < RPT; r++) {            // X4 write -> B (own rows only)
            int a = baseR + r;
            bReB[a] = vre[r]; bImB[a] = vim[r];
        }
        __syncthreads();
        {
            // gather to L0 with CNOT-ring sigma folded in (verified constants)
            const int SIGC[RPT] = {0x000, 0x300, 0x600, 0x500,
                                   0xC00, 0xF00, 0xA00, 0x900};
#pragma unroll
            for (int r = 0; r < RPT; r++) {
                int j = SIGC[r] ^ sig_t;
                int a = j + (j >> 3);              // == (j>>3)*9 + (j&7)
                vre[r] = bReB[a]; vim[r] = bImB[a];
            }
        }
    }

    // ---- expectations <Z_q>, both elements at once (registers only) ----
    u64 acc[NQ];
#pragma unroll
    for (int q = 0; q < NQ; q++) acc[q] = 0;
#pragma unroll
    for (int r = 0; r < RPT; r++) {
        u64 p2 = f2fma(vre[r], vre[r], f2mul(vim[r], vim[r]));
        u64 pn = p2 ^ 0x8000000080000000ULL;       // exact negation of both halves
        const int i = (r << 9) | tid;
#pragma unroll
        for (int q = 0; q < NQ; q++) {
            acc[q] = f2add(acc[q], ((i >> (11 - q)) & 1) ? pn : p2);
        }
    }
#pragma unroll
    for (int q = 0; q < NQ; q++) {
#pragma unroll
        for (int o = 16; o; o >>= 1)
            acc[q] = f2add(acc[q], __shfl_xor_sync(0xffffffffu, acc[q], o));
    }
    if ((tid & 31) == 0) {
#pragma unroll
        for (int q = 0; q < NQ; q++) {
            float p0, p1; unpk2(acc[q], p0, p1);
            atomicAdd(&sAcc[q], p0);
            atomicAdd(&sAcc[NQ + q], p1);
        }
    }
    __syncthreads();
    if (tid < NQ) {
        out[(size_t)(2 * bid) * NQ + tid] = sAcc[tid];
        out[(size_t)(2 * bid + 1) * NQ + tid] = sAcc[NQ + tid];
    }
}

extern "C" void kernel_launch(void* const* d_in, const int* in_sizes, int n_in,
                              void* d_out, int out_size) {
    const float* x = (const float*)d_in[0];       // (8192, 4096) float32
    const float* params = (const float*)d_in[1];  // (108,) float32
    float* out = (float*)d_out;                   // (8192, 12) float32
    const int batch = in_sizes[0] / DIM;
    const int smem_bytes = 4 * BUF * (int)sizeof(u64); // 147456

    cudaFuncSetAttribute(qsim_kernel, cudaFuncAttributeMaxDynamicSharedMemorySize,
                         smem_bytes);
    prep_gates<<<1, 64>>>(params);
    qsim_kernel<<<batch / 2, TPB, smem_bytes>>>(x, out);
}